// round 11
// baseline (speedup 1.0000x reference)
#include <cuda_runtime.h>

#define B_TOT  2048
#define T_LEN  512
#define IN_SZ  20
#define H      64
#define G4     256
#define BTILE  16
#define BSUB   8
#define NTHR   512
#define WSTR   257   // padded gate-stride for transposed weights (conflict-free init stores)

// smem layout (floats)
#define OFF_WHH0  0
#define OFF_WIH1  (OFF_WHH0 + H*WSTR)
#define OFF_WHH1  (OFF_WIH1 + H*WSTR)
#define OFF_GS    (OFF_WHH1 + H*WSTR)          // [16][256] activated gates
#define OFF_H0    (OFF_GS   + BTILE*G4)        // [16][64]
#define OFF_H1    (OFF_H0   + BTILE*H)         // [16][64]
#define OFF_XS    (OFF_H1   + BTILE*H)         // [2][16][20]
#define SMEM_FLOATS (OFF_XS + 2*BTILE*IN_SZ)
#define SMEM_BYTES  (SMEM_FLOATS * 4)

__device__ __forceinline__ float sigmoid_f(float x) {
    // exp overflow -> inf -> 1/(1+inf)=0 : correct limits, no NaN
    return 1.0f / (1.0f + __expf(-x));
}
__device__ __forceinline__ float tanh_f(float x) {
    float xx = fmaxf(x, -15.0f);           // avoid inf/inf NaN for very negative x
    float t  = __expf(-2.0f * xx);
    return __fdividef(1.0f - t, 1.0f + t);
}

__global__ void __launch_bounds__(NTHR, 1) lstm2_kernel(
    const float* __restrict__ x,
    const float* __restrict__ w_ih0, const float* __restrict__ w_hh0,
    const float* __restrict__ b_ih0, const float* __restrict__ b_hh0,
    const float* __restrict__ w_ih1, const float* __restrict__ w_hh1,
    const float* __restrict__ b_ih1, const float* __restrict__ b_hh1,
    const float* __restrict__ w_out, const float* __restrict__ b_out,
    float* __restrict__ out)
{
    extern __shared__ float sm[];
    float* whh0T = sm + OFF_WHH0;   // [64][257], element [j*WSTR + g]
    float* wih1T = sm + OFF_WIH1;
    float* whh1T = sm + OFF_WHH1;
    float* Gs    = sm + OFF_GS;     // [b][256]
    float* h0s   = sm + OFF_H0;     // [b][64]
    float* h1s   = sm + OFF_H1;     // [b][64]
    float* xs    = sm + OFF_XS;     // [2][16][20]

    const int tid   = threadIdx.x;
    const int g     = tid & 255;
    const int half  = tid >> 8;       // 0: batches 0-7 of tile, 1: 8-15
    const int bbase = half * BSUB;
    const int batch0 = blockIdx.x * BTILE;

    // ---- load weights transposed into smem (coalesced LDG, conflict-free STS) ----
    for (int idx = tid; idx < H * G4; idx += NTHR) {
        int j  = idx & (H - 1);
        int gg = idx >> 6;
        whh0T[j * WSTR + gg] = w_hh0[idx];
        wih1T[j * WSTR + gg] = w_ih1[idx];
        whh1T[j * WSTR + gg] = w_hh1[idx];
    }
    // zero h state (h0s and h1s are contiguous)
    for (int idx = tid; idx < 2 * BTILE * H; idx += NTHR) h0s[idx] = 0.0f;

    // per-thread cached row of w_ih0 (20 floats) + fused biases
    float4 w0r[5];
    {
        const float4* p = reinterpret_cast<const float4*>(w_ih0 + g * IN_SZ);
#pragma unroll
        for (int k = 0; k < 5; k++) w0r[k] = p[k];
    }
    const float bias0r = b_ih0[g] + b_hh0[g];
    const float bias1r = b_ih1[g] + b_hh1[g];

    // x prefetch mapping (320 floats/step; thread = b*20+k)
    const int xpb = tid / IN_SZ, xk = tid - xpb * IN_SZ;
    float xpre = 0.0f;
    if (tid < BTILE * IN_SZ) {
        xpre = x[((batch0 + xpb) * T_LEN + 0) * IN_SZ + xk];
        xs[tid] = xpre;                 // buffer 0 = t0
    }
    __syncthreads();

    float c0[2] = {0.0f, 0.0f};
    float c1[2] = {0.0f, 0.0f};
    const int uu = tid & 63;            // hidden unit for cell update
    const int qq = (tid >> 6) & 3;      // batch sub-group for cell update
    const bool ist = (g >= 128) && (g < 192);   // tanh gate (warp-uniform)

    for (int t = 0; t < T_LEN; t++) {
        const int cur = t & 1;
        // prefetch next timestep's x slice into a register
        if (tid < BTILE * IN_SZ && t + 1 < T_LEN)
            xpre = x[((batch0 + xpb) * T_LEN + (t + 1)) * IN_SZ + xk];

        const float* xsc = xs + cur * (BTILE * IN_SZ) + bbase * IN_SZ;
        const float* h0b = h0s + bbase * H;
        const float* h1b = h1s + bbase * H;

        // ================= layer 0 gates =================
        float acc[BSUB];
#pragma unroll
        for (int b = 0; b < BSUB; b++) acc[b] = bias0r;

#pragma unroll
        for (int kc = 0; kc < 5; kc++) {
            float4 w4 = w0r[kc];
#pragma unroll
            for (int b = 0; b < BSUB; b++) {
                float4 xv = reinterpret_cast<const float4*>(xsc + b * IN_SZ)[kc];
                acc[b] = fmaf(xv.x, w4.x, fmaf(xv.y, w4.y,
                         fmaf(xv.z, w4.z, fmaf(xv.w, w4.w, acc[b]))));
            }
        }
#pragma unroll 4
        for (int jc = 0; jc < 16; jc++) {
            const float* wp = whh0T + (4 * jc) * WSTR + g;
            float wv0 = wp[0], wv1 = wp[WSTR], wv2 = wp[2 * WSTR], wv3 = wp[3 * WSTR];
#pragma unroll
            for (int b = 0; b < BSUB; b++) {
                float4 hv = reinterpret_cast<const float4*>(h0b + b * H)[jc];
                acc[b] = fmaf(hv.x, wv0, fmaf(hv.y, wv1,
                         fmaf(hv.z, wv2, fmaf(hv.w, wv3, acc[b]))));
            }
        }
#pragma unroll
        for (int b = 0; b < BSUB; b++) {
            float a = ist ? tanh_f(acc[b]) : sigmoid_f(acc[b]);
            Gs[(bbase + b) * G4 + g] = a;
        }
        __syncthreads();

        // ================= layer 0 cell update =================
#pragma unroll
        for (int s = 0; s < 2; s++) {
            int b = bbase + qq * 2 + s;
            const float* gr = Gs + b * G4 + uu;
            float iv = gr[0], fv = gr[64], gv = gr[128], ov = gr[192];
            float c = fmaf(fv, c0[s], iv * gv);
            c0[s] = c;
            h0s[b * H + uu] = ov * tanh_f(c);
        }
        __syncthreads();

        // ================= layer 1 gates =================
#pragma unroll
        for (int b = 0; b < BSUB; b++) acc[b] = bias1r;
#pragma unroll 4
        for (int jc = 0; jc < 16; jc++) {
            const float* wp = wih1T + (4 * jc) * WSTR + g;
            float wv0 = wp[0], wv1 = wp[WSTR], wv2 = wp[2 * WSTR], wv3 = wp[3 * WSTR];
#pragma unroll
            for (int b = 0; b < BSUB; b++) {
                float4 hv = reinterpret_cast<const float4*>(h0b + b * H)[jc];
                acc[b] = fmaf(hv.x, wv0, fmaf(hv.y, wv1,
                         fmaf(hv.z, wv2, fmaf(hv.w, wv3, acc[b]))));
            }
        }
#pragma unroll 4
        for (int jc = 0; jc < 16; jc++) {
            const float* wp = whh1T + (4 * jc) * WSTR + g;
            float wv0 = wp[0], wv1 = wp[WSTR], wv2 = wp[2 * WSTR], wv3 = wp[3 * WSTR];
#pragma unroll
            for (int b = 0; b < BSUB; b++) {
                float4 hv = reinterpret_cast<const float4*>(h1b + b * H)[jc];
                acc[b] = fmaf(hv.x, wv0, fmaf(hv.y, wv1,
                         fmaf(hv.z, wv2, fmaf(hv.w, wv3, acc[b]))));
            }
        }
#pragma unroll
        for (int b = 0; b < BSUB; b++) {
            float a = ist ? tanh_f(acc[b]) : sigmoid_f(acc[b]);
            Gs[(bbase + b) * G4 + g] = a;
        }
        __syncthreads();

        // ================= layer 1 cell update + x double-buffer commit =================
#pragma unroll
        for (int s = 0; s < 2; s++) {
            int b = bbase + qq * 2 + s;
            const float* gr = Gs + b * G4 + uu;
            float iv = gr[0], fv = gr[64], gv = gr[128], ov = gr[192];
            float c = fmaf(fv, c1[s], iv * gv);
            c1[s] = c;
            h1s[b * H + uu] = ov * tanh_f(c);
        }
        if (tid < BTILE * IN_SZ && t + 1 < T_LEN)
            xs[(cur ^ 1) * (BTILE * IN_SZ) + tid] = xpre;
        __syncthreads();
    }

    // ================= output projection: out[b] = h1 @ w_out^T + b_out =================
    if (tid < BTILE * 5) {
        int b = tid / 5, o = tid - 5 * b;
        float s = b_out[o];
        const float* hr = h1s + b * H;
        const float* wr = w_out + o * H;
#pragma unroll 16
        for (int u = 0; u < H; u++) s = fmaf(hr[u], wr[u], s);
        out[(batch0 + b) * 5 + o] = s;
    }
}

extern "C" void kernel_launch(void* const* d_in, const int* in_sizes, int n_in,
                              void* d_out, int out_size) {
    const float* x     = (const float*)d_in[0];
    const float* w_ih0 = (const float*)d_in[1];
    const float* w_hh0 = (const float*)d_in[2];
    const float* b_ih0 = (const float*)d_in[3];
    const float* b_hh0 = (const float*)d_in[4];
    const float* w_ih1 = (const float*)d_in[5];
    const float* w_hh1 = (const float*)d_in[6];
    const float* b_ih1 = (const float*)d_in[7];
    const float* b_hh1 = (const float*)d_in[8];
    const float* w_out = (const float*)d_in[9];
    const float* b_out = (const float*)d_in[10];
    float* out = (float*)d_out;

    cudaFuncSetAttribute(lstm2_kernel, cudaFuncAttributeMaxDynamicSharedMemorySize, SMEM_BYTES);
    lstm2_kernel<<<B_TOT / BTILE, NTHR, SMEM_BYTES>>>(
        x, w_ih0, w_hh0, b_ih0, b_hh0,
        w_ih1, w_hh1, b_ih1, b_hh1,
        w_out, b_out, out);
}

// round 12
// speedup vs baseline: 1.3121x; 1.3121x over previous
#include <cuda_runtime.h>

typedef unsigned long long u64;

#define B_TOT 2048
#define T_LEN 512
#define IN_SZ 20
#define H     64
#define BTILE 16
#define NTHR  256

// ---- smem layout (float offsets) ----
#define OFF_W0   0                  // whh0^T  [64 j][64 u][4 gates] = 16384
#define OFF_W1I  16384              // wih1^T  same
#define OFF_W1H  32768              // whh1^T  same
#define OFF_H0   49152              // h0 [64 j][20 (16 used)] = 1280
#define OFF_H1   50432              // h1 [64][20] = 1280
#define OFF_XS   51712              // x  [2][20 k][16 b] = 640
#define OFF_PART 52352              // u64 partials [32 rows][64 u] = 2048 u64 = 4096 fl
#define SMEM_FLOATS 56448
#define SMEM_BYTES  (SMEM_FLOATS*4) // 225792 B

__device__ __forceinline__ u64 dup2(float v){ u64 r; asm("mov.b64 %0,{%1,%1};":"=l"(r):"f"(v)); return r; }
__device__ __forceinline__ void fma2(u64& d, u64 a, u64 b){ asm("fma.rn.f32x2 %0,%1,%2,%0;":"+l"(d):"l"(a),"l"(b)); }
__device__ __forceinline__ u64 add2(u64 a, u64 b){ u64 r; asm("add.rn.f32x2 %0,%1,%2;":"=l"(r):"l"(a),"l"(b)); return r; }
__device__ __forceinline__ void unpk(u64 v, float& lo, float& hi){ asm("mov.b64 {%0,%1},%2;":"=f"(lo),"=f"(hi):"l"(v)); }

__device__ __forceinline__ float sigmoid_f(float v){ return 1.0f/(1.0f+__expf(-v)); }
__device__ __forceinline__ float tanh_f(float v){
    float xx = fmaxf(v, -15.0f);
    float t  = __expf(-2.0f*xx);
    return __fdividef(1.0f - t, 1.0f + t);
}

__global__ void __launch_bounds__(NTHR,1) lstm2_kernel(
    const float* __restrict__ x,
    const float* __restrict__ w_ih0, const float* __restrict__ w_hh0,
    const float* __restrict__ b_ih0, const float* __restrict__ b_hh0,
    const float* __restrict__ w_ih1, const float* __restrict__ w_hh1,
    const float* __restrict__ b_ih1, const float* __restrict__ b_hh1,
    const float* __restrict__ w_out, const float* __restrict__ b_out,
    float* __restrict__ out)
{
    extern __shared__ float sm[];
    float* W0  = sm + OFF_W0;
    float* W1I = sm + OFF_W1I;
    float* W1H = sm + OFF_W1H;
    float* h0s = sm + OFF_H0;
    float* h1s = sm + OFF_H1;
    float* xsm = sm + OFF_XS;
    u64*   part = (u64*)(sm + OFF_PART);

    const int tid  = threadIdx.x;
    const int lane = tid & 31;
    const int wid  = tid >> 5;
    const int uw   = wid & 1;
    const int bg   = (wid >> 1) & 1;
    const int kh   = wid >> 2;          // 0/1 : K-half
    const int u    = uw * 32 + lane;    // hidden unit this thread owns
    const int b8   = bg * 8;            // batch sub-offset (8 batches)
    const int batch0 = blockIdx.x * BTILE;
    const int kh32 = kh * 32;

    // ---- transpose weights into smem: dst[(j*64+u)*4 + gate] (one-time) ----
    for (int idx = tid; idx < 4*H*H; idx += NTHR) {
        int g = idx >> 6, j = idx & 63;
        int dst = ((j << 6) + (g & 63)) * 4 + (g >> 6);
        W0 [dst] = w_hh0[idx];
        W1I[dst] = w_ih1[idx];
        W1H[dst] = w_hh1[idx];
    }
    // zero h0s + h1s (contiguous 2560 floats)
    for (int idx = tid; idx < 2*H*20; idx += NTHR) h0s[idx] = 0.0f;
    // x buffer 0 = t0 (transposed [k][b])
    for (int idx = tid; idx < BTILE*IN_SZ; idx += NTHR) {
        int b = idx / IN_SZ, k = idx - b*IN_SZ;
        xsm[k*16 + b] = x[(batch0 + b) * (T_LEN*IN_SZ) + k];
    }

    // ---- register-cached w_ih0 rows (this thread's 4 gates, its K-half of 10) ----
    float w0r[4][10];
#pragma unroll
    for (int m = 0; m < 4; m++)
#pragma unroll
        for (int kk = 0; kk < 10; kk++)
            w0r[m][kk] = w_ih0[(u + 64*m)*IN_SZ + kh*10 + kk];

    // fused biases (used by kh==0 at activation time)
    float bs0[4], bs1[4];
#pragma unroll
    for (int m = 0; m < 4; m++) {
        bs0[m] = b_ih0[u + 64*m] + b_hh0[u + 64*m];
        bs1[m] = b_ih1[u + 64*m] + b_hh1[u + 64*m];
    }
    float c0[8], c1[8];
#pragma unroll
    for (int i = 0; i < 8; i++) { c0[i] = 0.0f; c1[i] = 0.0f; }

    // x prefetch mapping (kh==1 warps only): fixed (b,k) per thread
    const int tloc = tid - 128;
    const int ba0 = tloc / 20,        ka0 = tloc - 20*ba0;
    const int ba1 = (tloc+128) / 20,  ka1 = (tloc+128) - 20*ba1;
    const int ba2 = (tloc+256) / 20,  ka2 = (tloc+256) - 20*ba2;

    __syncthreads();

    for (int t = 0; t < T_LEN; t++) {
        const int cur = t & 1;

        // issue next-step x LDGs early (kh1 warps)
        float xp0 = 0.f, xp1 = 0.f, xp2 = 0.f;
        if (kh && t + 1 < T_LEN) {
            xp0 = x[(batch0 + ba0)*(T_LEN*IN_SZ) + (t+1)*IN_SZ + ka0];
            xp1 = x[(batch0 + ba1)*(T_LEN*IN_SZ) + (t+1)*IN_SZ + ka1];
            if (tloc < 64)
                xp2 = x[(batch0 + ba2)*(T_LEN*IN_SZ) + (t+1)*IN_SZ + ka2];
        }

        // ================= layer 0 gate partials =================
        u64 acc[4][4];
#pragma unroll
        for (int g = 0; g < 4; g++) { acc[g][0]=0ull; acc[g][1]=0ull; acc[g][2]=0ull; acc[g][3]=0ull; }

        // x part (k-half of 10)
        {
            const float* xrow = xsm + cur*320;
#pragma unroll
            for (int kk = 0; kk < 10; kk++) {
                const ulonglong2* xp = (const ulonglong2*)(xrow + (kh*10 + kk)*16 + b8);
                ulonglong2 xa = xp[0], xb = xp[1];
#pragma unroll
                for (int m = 0; m < 4; m++) {
                    u64 wp = dup2(w0r[m][kk]);
                    fma2(acc[m][0], wp, xa.x); fma2(acc[m][1], wp, xa.y);
                    fma2(acc[m][2], wp, xb.x); fma2(acc[m][3], wp, xb.y);
                }
            }
        }
        // h part (j-half of 32)
#pragma unroll 4
        for (int j = 0; j < 32; j++) {
            int jj = kh32 + j;
            float4 w4 = *(const float4*)(W0 + (jj << 8) + (u << 2));
            const ulonglong2* hp = (const ulonglong2*)(h0s + jj*20 + b8);
            ulonglong2 ha = hp[0], hb = hp[1];
            u64 p0 = dup2(w4.x), p1 = dup2(w4.y), p2 = dup2(w4.z), p3 = dup2(w4.w);
            fma2(acc[0][0],p0,ha.x); fma2(acc[0][1],p0,ha.y); fma2(acc[0][2],p0,hb.x); fma2(acc[0][3],p0,hb.y);
            fma2(acc[1][0],p1,ha.x); fma2(acc[1][1],p1,ha.y); fma2(acc[1][2],p1,hb.x); fma2(acc[1][3],p1,hb.y);
            fma2(acc[2][0],p2,ha.x); fma2(acc[2][1],p2,ha.y); fma2(acc[2][2],p2,hb.x); fma2(acc[2][3],p2,hb.y);
            fma2(acc[3][0],p3,ha.x); fma2(acc[3][1],p3,ha.y); fma2(acc[3][2],p3,hb.x); fma2(acc[3][3],p3,hb.y);
        }

        if (kh) {   // write partials (conflict-free STS.64: lanes = consecutive u)
#pragma unroll
            for (int g = 0; g < 4; g++)
#pragma unroll
                for (int p = 0; p < 4; p++)
                    part[((g*8 + bg*4 + p) << 6) + u] = acc[g][p];
        }
        __syncthreads();

        if (!kh) {
            // reduce + activate + cell update + h0 store (thread-local!)
            float pre[4][8];
#pragma unroll
            for (int g = 0; g < 4; g++)
#pragma unroll
                for (int p = 0; p < 4; p++) {
                    u64 s = add2(acc[g][p], part[((g*8 + bg*4 + p) << 6) + u]);
                    unpk(s, pre[g][2*p], pre[g][2*p+1]);
                }
            float hn[8];
#pragma unroll
            for (int bb = 0; bb < 8; bb++) {
                float iv = sigmoid_f(pre[0][bb] + bs0[0]);
                float fv = sigmoid_f(pre[1][bb] + bs0[1]);
                float gv = tanh_f   (pre[2][bb] + bs0[2]);
                float ov = sigmoid_f(pre[3][bb] + bs0[3]);
                float c  = fmaf(fv, c0[bb], iv * gv);
                c0[bb] = c;
                hn[bb] = ov * tanh_f(c);
            }
            *(float4*)(h0s + u*20 + b8)     = make_float4(hn[0],hn[1],hn[2],hn[3]);
            *(float4*)(h0s + u*20 + b8 + 4) = make_float4(hn[4],hn[5],hn[6],hn[7]);
        } else if (t + 1 < T_LEN) {
            // commit prefetched x into the other buffer
            float* xd = xsm + (1 - cur)*320;
            xd[ka0*16 + ba0] = xp0;
            xd[ka1*16 + ba1] = xp1;
            if (tloc < 64) xd[ka2*16 + ba2] = xp2;
        }
        __syncthreads();

        // ================= layer 1 gate partials =================
#pragma unroll
        for (int g = 0; g < 4; g++) { acc[g][0]=0ull; acc[g][1]=0ull; acc[g][2]=0ull; acc[g][3]=0ull; }

#pragma unroll 4
        for (int j = 0; j < 32; j++) {
            int jj = kh32 + j;
            float4 wa = *(const float4*)(W1I + (jj << 8) + (u << 2));
            float4 wb = *(const float4*)(W1H + (jj << 8) + (u << 2));
            const ulonglong2* h0p = (const ulonglong2*)(h0s + jj*20 + b8);
            const ulonglong2* h1p = (const ulonglong2*)(h1s + jj*20 + b8);
            ulonglong2 a0 = h0p[0], a1 = h0p[1];
            ulonglong2 d0 = h1p[0], d1 = h1p[1];
            {
                u64 p0=dup2(wa.x), p1=dup2(wa.y), p2=dup2(wa.z), p3=dup2(wa.w);
                fma2(acc[0][0],p0,a0.x); fma2(acc[0][1],p0,a0.y); fma2(acc[0][2],p0,a1.x); fma2(acc[0][3],p0,a1.y);
                fma2(acc[1][0],p1,a0.x); fma2(acc[1][1],p1,a0.y); fma2(acc[1][2],p1,a1.x); fma2(acc[1][3],p1,a1.y);
                fma2(acc[2][0],p2,a0.x); fma2(acc[2][1],p2,a0.y); fma2(acc[2][2],p2,a1.x); fma2(acc[2][3],p2,a1.y);
                fma2(acc[3][0],p3,a0.x); fma2(acc[3][1],p3,a0.y); fma2(acc[3][2],p3,a1.x); fma2(acc[3][3],p3,a1.y);
            }
            {
                u64 p0=dup2(wb.x), p1=dup2(wb.y), p2=dup2(wb.z), p3=dup2(wb.w);
                fma2(acc[0][0],p0,d0.x); fma2(acc[0][1],p0,d0.y); fma2(acc[0][2],p0,d1.x); fma2(acc[0][3],p0,d1.y);
                fma2(acc[1][0],p1,d0.x); fma2(acc[1][1],p1,d0.y); fma2(acc[1][2],p1,d1.x); fma2(acc[1][3],p1,d1.y);
                fma2(acc[2][0],p2,d0.x); fma2(acc[2][1],p2,d0.y); fma2(acc[2][2],p2,d1.x); fma2(acc[2][3],p2,d1.y);
                fma2(acc[3][0],p3,d0.x); fma2(acc[3][1],p3,d0.y); fma2(acc[3][2],p3,d1.x); fma2(acc[3][3],p3,d1.y);
            }
        }

        if (kh) {
#pragma unroll
            for (int g = 0; g < 4; g++)
#pragma unroll
                for (int p = 0; p < 4; p++)
                    part[((g*8 + bg*4 + p) << 6) + u] = acc[g][p];
        }
        __syncthreads();

        if (!kh) {
            float pre[4][8];
#pragma unroll
            for (int g = 0; g < 4; g++)
#pragma unroll
                for (int p = 0; p < 4; p++) {
                    u64 s = add2(acc[g][p], part[((g*8 + bg*4 + p) << 6) + u]);
                    unpk(s, pre[g][2*p], pre[g][2*p+1]);
                }
            float hn[8];
#pragma unroll
            for (int bb = 0; bb < 8; bb++) {
                float iv = sigmoid_f(pre[0][bb] + bs1[0]);
                float fv = sigmoid_f(pre[1][bb] + bs1[1]);
                float gv = tanh_f   (pre[2][bb] + bs1[2]);
                float ov = sigmoid_f(pre[3][bb] + bs1[3]);
                float c  = fmaf(fv, c1[bb], iv * gv);
                c1[bb] = c;
                hn[bb] = ov * tanh_f(c);
            }
            *(float4*)(h1s + u*20 + b8)     = make_float4(hn[0],hn[1],hn[2],hn[3]);
            *(float4*)(h1s + u*20 + b8 + 4) = make_float4(hn[4],hn[5],hn[6],hn[7]);
        }
        __syncthreads();
    }

    // ================= output projection =================
    if (tid < BTILE*5) {
        int b = tid / 5, o = tid - 5*b;
        float s = b_out[o];
        const float* wr = w_out + o*H;
#pragma unroll 16
        for (int uu = 0; uu < H; uu++) s = fmaf(h1s[uu*20 + b], wr[uu], s);
        out[(batch0 + b)*5 + o] = s;
    }
}

extern "C" void kernel_launch(void* const* d_in, const int* in_sizes, int n_in,
                              void* d_out, int out_size) {
    const float* x     = (const float*)d_in[0];
    const float* w_ih0 = (const float*)d_in[1];
    const float* w_hh0 = (const float*)d_in[2];
    const float* b_ih0 = (const float*)d_in[3];
    const float* b_hh0 = (const float*)d_in[4];
    const float* w_ih1 = (const float*)d_in[5];
    const float* w_hh1 = (const float*)d_in[6];
    const float* b_ih1 = (const float*)d_in[7];
    const float* b_hh1 = (const float*)d_in[8];
    const float* w_out = (const float*)d_in[9];
    const float* b_out = (const float*)d_in[10];
    float* out = (float*)d_out;

    cudaFuncSetAttribute(lstm2_kernel, cudaFuncAttributeMaxDynamicSharedMemorySize, SMEM_BYTES);
    lstm2_kernel<<<B_TOT / BTILE, NTHR, SMEM_BYTES>>>(
        x, w_ih0, w_hh0, b_ih0, b_hh0,
        w_ih1, w_hh1, b_ih1, b_hh1,
        w_out, b_out, out);
}

// round 13
// speedup vs baseline: 1.5970x; 1.2172x over previous
#include <cuda_runtime.h>

typedef unsigned long long u64;

#define B_TOT 2048
#define T_LEN 512
#define IN_SZ 20
#define H     64
#define BTILE 16
#define NTHR  512

// ---- smem layout (float offsets) ----
#define OFF_W0   0                  // whh0^T  [64 j][64 u][4 g] = 16384
#define OFF_W1I  16384
#define OFF_W1H  32768
#define OFF_H0   49152              // h0 [2 buf][64 u][20 (16 used)] = 2560
#define OFF_H1   51712              // h1 [2][64][20] = 2560
#define OFF_XS   54272              // x  [2][20 k][16 b] = 640
#define SMEM_FLOATS 54912
#define SMEM_BYTES  (SMEM_FLOATS*4) // 219648 B

__device__ __forceinline__ u64 dup2(float v){ u64 r; asm("mov.b64 %0,{%1,%1};":"=l"(r):"f"(v)); return r; }
__device__ __forceinline__ void fma2(u64& d, u64 a, u64 b){ asm("fma.rn.f32x2 %0,%1,%2,%0;":"+l"(d):"l"(a),"l"(b)); }
__device__ __forceinline__ u64 add2(u64 a, u64 b){ u64 r; asm("add.rn.f32x2 %0,%1,%2;":"=l"(r):"l"(a),"l"(b)); return r; }
__device__ __forceinline__ void unpk(u64 v, float& lo, float& hi){ asm("mov.b64 {%0,%1},%2;":"=f"(lo),"=f"(hi):"l"(v)); }

__device__ __forceinline__ float sigmoid_f(float v){ return 1.0f/(1.0f+__expf(-v)); }
__device__ __forceinline__ float tanh_f(float v){
    float xx = fmaxf(v, -15.0f);
    float t  = __expf(-2.0f*xx);
    return __fdividef(1.0f - t, 1.0f + t);
}

__global__ void __launch_bounds__(NTHR,1) lstm2_kernel(
    const float* __restrict__ x,
    const float* __restrict__ w_ih0, const float* __restrict__ w_hh0,
    const float* __restrict__ b_ih0, const float* __restrict__ b_hh0,
    const float* __restrict__ w_ih1, const float* __restrict__ w_hh1,
    const float* __restrict__ b_ih1, const float* __restrict__ b_hh1,
    const float* __restrict__ w_out, const float* __restrict__ b_out,
    float* __restrict__ out)
{
    extern __shared__ float sm[];
    float* W0  = sm + OFF_W0;
    float* W1I = sm + OFF_W1I;
    float* W1H = sm + OFF_W1H;
    float* h0b = sm + OFF_H0;
    float* h1b = sm + OFF_H1;
    float* xsm = sm + OFF_XS;

    const int tid    = threadIdx.x;
    const int lane   = tid & 31;
    const int wid    = tid >> 5;
    const int ul     = lane & 7;
    const int bgl    = (lane >> 3) & 1;
    const int kh     = lane >> 4;          // K-half, intra-warp (bit 4)
    const int uh     = wid & 7;
    const int bgo    = wid >> 3;
    const int u      = uh * 8 + ul;        // hidden unit
    const int g4     = bgo * 2 + bgl;      // 4-batch group 0..3
    const int bown   = g4 * 4 + kh * 2;    // first owned batch (local in tile)
    const int batch0 = blockIdx.x * BTILE;

    // ---- weight transpose into smem: dst[(j*64+u)*4 + gate] ----
    for (int idx = tid; idx < 4*H*H; idx += NTHR) {
        int g = idx >> 6, j = idx & 63;
        int dst = ((j << 6) + (g & 63)) * 4 + (g >> 6);
        W0 [dst] = w_hh0[idx];
        W1I[dst] = w_ih1[idx];
        W1H[dst] = w_hh1[idx];
    }
    // zero h buffers (contiguous 5120 floats)
    for (int idx = tid; idx < 5120; idx += NTHR) h0b[idx] = 0.0f;
    // x t=0 into buffer 0 ([k][b])
    if (tid < BTILE*IN_SZ) {
        int b = tid / IN_SZ, k = tid - b*IN_SZ;
        xsm[k*16 + b] = x[(batch0 + b) * (T_LEN*IN_SZ) + k];
    }

    // per-thread w_ih0 rows: this u's 4 gates, its interleaved K-half (k = 2kk+kh)
    float w0r[4][10];
#pragma unroll
    for (int m = 0; m < 4; m++)
#pragma unroll
        for (int kk = 0; kk < 10; kk++)
            w0r[m][kk] = w_ih0[(m*64 + u)*IN_SZ + 2*kk + kh];

    float bs0[4], bs1[4];
#pragma unroll
    for (int m = 0; m < 4; m++) {
        bs0[m] = b_ih0[m*64 + u] + b_hh0[m*64 + u];
        bs1[m] = b_ih1[m*64 + u] + b_hh1[m*64 + u];
    }
    float c0[2] = {0.f, 0.f}, c1[2] = {0.f, 0.f};

    // x prefetch mapping
    const bool xth = tid < BTILE*IN_SZ;
    const int  xb  = xth ? tid / IN_SZ : 0;
    const int  xk  = xth ? tid - xb*IN_SZ : 0;

    __syncthreads();

    for (int t = 0; t < T_LEN; t++) {
        const int cur = t & 1, prv = cur ^ 1;

        float xpre = 0.0f;
        if (xth && t + 1 < T_LEN)
            xpre = x[(batch0 + xb)*(T_LEN*IN_SZ) + (t+1)*IN_SZ + xk];

        const float* h0r = h0b + prv*1280;

        // ================= layer 0 gates =================
        u64 a0[4] = {0,0,0,0}, a1[4] = {0,0,0,0};   // mem-pair0 / mem-pair1

        // x part: k = 2kk + kh
#pragma unroll
        for (int kk = 0; kk < 10; kk++) {
            ulonglong2 xv = *(const ulonglong2*)(xsm + cur*320 + (2*kk + kh)*16 + g4*4);
#pragma unroll
            for (int m = 0; m < 4; m++) {
                u64 w = dup2(w0r[m][kk]);
                fma2(a0[m], w, xv.x);
                fma2(a1[m], w, xv.y);
            }
        }
        // h part: j = 2*j0 + kh
#pragma unroll 8
        for (int j0 = 0; j0 < 32; j0++) {
            int j = 2*j0 + kh;
            float4 w4 = *(const float4*)(W0 + (j << 8) + (u << 2));
            ulonglong2 hv = *(const ulonglong2*)(h0r + j*20 + g4*4);
            u64 p0 = dup2(w4.x), p1 = dup2(w4.y), p2 = dup2(w4.z), p3 = dup2(w4.w);
            fma2(a0[0],p0,hv.x); fma2(a1[0],p0,hv.y);
            fma2(a0[1],p1,hv.x); fma2(a1[1],p1,hv.y);
            fma2(a0[2],p2,hv.x); fma2(a1[2],p2,hv.y);
            fma2(a0[3],p3,hv.x); fma2(a1[3],p3,hv.y);
        }
        // shuffle K-reduce: own = owned mem-pair (index kh), partner holds other K-half
        {
            float hn0, hn1;
            float pre[4][2];
#pragma unroll
            for (int m = 0; m < 4; m++) {
                u64 own = kh ? a1[m] : a0[m];
                u64 oth = kh ? a0[m] : a1[m];
                u64 r = __shfl_xor_sync(0xffffffffu, oth, 16);
                own = add2(own, r);
                unpk(own, pre[m][0], pre[m][1]);
            }
#pragma unroll
            for (int s = 0; s < 2; s++) {
                float iv = sigmoid_f(pre[0][s] + bs0[0]);
                float fv = sigmoid_f(pre[1][s] + bs0[1]);
                float gv = tanh_f   (pre[2][s] + bs0[2]);
                float ov = sigmoid_f(pre[3][s] + bs0[3]);
                float c  = fmaf(fv, c0[s], iv * gv);
                c0[s] = c;
                float hv2 = ov * tanh_f(c);
                if (s == 0) hn0 = hv2; else hn1 = hv2;
            }
            *(float2*)(h0b + cur*1280 + u*20 + bown) = make_float2(hn0, hn1);
        }
        __syncthreads();    // h0(t) ready

        const float* h0n = h0b + cur*1280;
        const float* h1r = h1b + prv*1280;

        // ================= layer 1 gates =================
#pragma unroll
        for (int m = 0; m < 4; m++) { a0[m] = 0ull; a1[m] = 0ull; }

#pragma unroll 4
        for (int j0 = 0; j0 < 32; j0++) {
            int j = 2*j0 + kh;
            float4 wa = *(const float4*)(W1I + (j << 8) + (u << 2));
            float4 wb = *(const float4*)(W1H + (j << 8) + (u << 2));
            ulonglong2 ha = *(const ulonglong2*)(h0n + j*20 + g4*4);
            ulonglong2 hb = *(const ulonglong2*)(h1r + j*20 + g4*4);
            {
                u64 p0 = dup2(wa.x), p1 = dup2(wa.y), p2 = dup2(wa.z), p3 = dup2(wa.w);
                fma2(a0[0],p0,ha.x); fma2(a1[0],p0,ha.y);
                fma2(a0[1],p1,ha.x); fma2(a1[1],p1,ha.y);
                fma2(a0[2],p2,ha.x); fma2(a1[2],p2,ha.y);
                fma2(a0[3],p3,ha.x); fma2(a1[3],p3,ha.y);
            }
            {
                u64 p0 = dup2(wb.x), p1 = dup2(wb.y), p2 = dup2(wb.z), p3 = dup2(wb.w);
                fma2(a0[0],p0,hb.x); fma2(a1[0],p0,hb.y);
                fma2(a0[1],p1,hb.x); fma2(a1[1],p1,hb.y);
                fma2(a0[2],p2,hb.x); fma2(a1[2],p2,hb.y);
                fma2(a0[3],p3,hb.x); fma2(a1[3],p3,hb.y);
            }
        }
        {
            float hn0, hn1;
            float pre[4][2];
#pragma unroll
            for (int m = 0; m < 4; m++) {
                u64 own = kh ? a1[m] : a0[m];
                u64 oth = kh ? a0[m] : a1[m];
                u64 r = __shfl_xor_sync(0xffffffffu, oth, 16);
                own = add2(own, r);
                unpk(own, pre[m][0], pre[m][1]);
            }
#pragma unroll
            for (int s = 0; s < 2; s++) {
                float iv = sigmoid_f(pre[0][s] + bs1[0]);
                float fv = sigmoid_f(pre[1][s] + bs1[1]);
                float gv = tanh_f   (pre[2][s] + bs1[2]);
                float ov = sigmoid_f(pre[3][s] + bs1[3]);
                float c  = fmaf(fv, c1[s], iv * gv);
                c1[s] = c;
                float hv2 = ov * tanh_f(c);
                if (s == 0) hn0 = hv2; else hn1 = hv2;
            }
            *(float2*)(h1b + cur*1280 + u*20 + bown) = make_float2(hn0, hn1);
        }
        // commit prefetched x into the other buffer (read next step by layer 0)
        if (xth && t + 1 < T_LEN)
            xsm[prv*320 + xk*16 + xb] = xpre;
        __syncthreads();    // h1(t), x(t+1) ready
    }

    // ================= output projection (h1 final at buffer (T_LEN-1)&1 = 1) =================
    if (tid < BTILE*5) {
        int b = tid / 5, o = tid - 5*b;
        float s = b_out[o];
        const float* hr = h1b + 1280 + b;   // stride 20 per u
        const float* wr = w_out + o*H;
#pragma unroll 16
        for (int uu = 0; uu < H; uu++) s = fmaf(hr[uu*20], wr[uu], s);
        out[(batch0 + b)*5 + o] = s;
    }
}

extern "C" void kernel_launch(void* const* d_in, const int* in_sizes, int n_in,
                              void* d_out, int out_size) {
    const float* x     = (const float*)d_in[0];
    const float* w_ih0 = (const float*)d_in[1];
    const float* w_hh0 = (const float*)d_in[2];
    const float* b_ih0 = (const float*)d_in[3];
    const float* b_hh0 = (const float*)d_in[4];
    const float* w_ih1 = (const float*)d_in[5];
    const float* w_hh1 = (const float*)d_in[6];
    const float* b_ih1 = (const float*)d_in[7];
    const float* b_hh1 = (const float*)d_in[8];
    const float* w_out = (const float*)d_in[9];
    const float* b_out = (const float*)d_in[10];
    float* out = (float*)d_out;

    cudaFuncSetAttribute(lstm2_kernel, cudaFuncAttributeMaxDynamicSharedMemorySize, SMEM_BYTES);
    lstm2_kernel<<<B_TOT / BTILE, NTHR, SMEM_BYTES>>>(
        x, w_ih0, w_hh0, b_ih0, b_hh0,
        w_ih1, w_hh1, b_ih1, b_hh1,
        w_out, b_out, out);
}